// round 7
// baseline (speedup 1.0000x reference)
#include <cuda_runtime.h>
#include <math.h>
#include <stdint.h>

// Problem constants
#define Bb   4
#define Tt   2048
#define Ee   512
#define Dd   512
#define Nn   16
#define Ll   4
#define TC   32              // chunk length (time steps per thread)
#define NCH  (Tt / TC)       // 64 chunks
#define DN   (Dd * Nn)       // 8192
#define DBLK 2               // d-channels per block in fused scan
#define SXS  34              // padded smem row stride (floats, even for ull)

typedef unsigned long long ull;

__device__ __forceinline__ ull pack2(float lo, float hi) {
    ull r; asm("mov.b64 %0, {%1,%2};" : "=l"(r) : "f"(lo), "f"(hi)); return r;
}
__device__ __forceinline__ void unpack2(ull v, float& lo, float& hi) {
    asm("mov.b64 {%0,%1}, %2;" : "=f"(lo), "=f"(hi) : "l"(v));
}
__device__ __forceinline__ ull fma2(ull a, ull b, ull c) {
    ull d; asm("fma.rn.f32x2 %0, %1, %2, %3;" : "=l"(d) : "l"(a), "l"(b), "l"(c));
    return d;
}
__device__ __forceinline__ uint32_t f2tf(float f) {
    uint32_t u; asm("cvt.rna.tf32.f32 %0, %1;" : "=r"(u) : "f"(f)); return u;
}
__device__ __forceinline__ void ldsm4(uint32_t& r0, uint32_t& r1, uint32_t& r2,
                                      uint32_t& r3, const uint32_t* p) {
    uint32_t a = (uint32_t)__cvta_generic_to_shared(p);
    asm volatile("ldmatrix.sync.aligned.m8n8.x4.shared.b16 {%0,%1,%2,%3}, [%4];"
                 : "=r"(r0), "=r"(r1), "=r"(r2), "=r"(r3) : "r"(a));
}
__device__ __forceinline__ void mma_tf32(float* c, const uint32_t* a,
                                         uint32_t b0, uint32_t b1) {
    asm volatile("mma.sync.aligned.m16n8k8.row.col.f32.tf32.tf32.f32 "
                 "{%0,%1,%2,%3}, {%4,%5,%6,%7}, {%8,%9}, {%0,%1,%2,%3};"
                 : "+f"(c[0]), "+f"(c[1]), "+f"(c[2]), "+f"(c[3])
                 : "r"(a[0]), "r"(a[1]), "r"(a[2]), "r"(a[3]), "r"(b0), "r"(b1));
}

// Scratch (static device globals; no runtime allocation)
__device__ float g_ht[(size_t)Bb * Dd * Tt];       // residual stream, TRANSPOSED [b][d][t]
__device__ float g_Abar [Ll * DN];
__device__ float g_CB   [Ll * DN];                 // C * Bbar
__device__ float g_AbarP[Ll * DN];                 // Abar^TC
__device__ float g_swf0[Dd], g_swen[Dd];           // scale*weight per head
__device__ float g_hc[4];                          // SWf0, BWf0, SWen, BWen

// ---------------------------------------------------------------------------
// Precompute per-layer SSM constants
// ---------------------------------------------------------------------------
__global__ void precompute_kernel(const float* __restrict__ A_log,
                                  const float* __restrict__ B_ssm,
                                  const float* __restrict__ C_ssm,
                                  const float* __restrict__ log_dt) {
    int idx = blockIdx.x * blockDim.x + threadIdx.x;
    if (idx >= Ll * DN) return;
    int l  = idx / DN;
    int dn = idx % DN;
    int d  = dn / Nn;
    float dt = expf(log_dt[l * Dd + d]);
    float A  = -expf(A_log[idx]);
    float dA = dt * A;
    float ab = expf(dA);
    g_Abar [idx] = ab;
    g_CB   [idx] = (ab - 1.0f) / A * B_ssm[idx] * C_ssm[idx];
    g_AbarP[idx] = expf(dA * (float)TC);
}

// ---------------------------------------------------------------------------
// Head precompute
// ---------------------------------------------------------------------------
__global__ void head_prep_kernel(const float* __restrict__ s_f0, const float* __restrict__ bi_f0,
                                 const float* __restrict__ w_f0,
                                 const float* __restrict__ s_en, const float* __restrict__ bi_en,
                                 const float* __restrict__ w_en) {
    __shared__ float red[4][16];
    int d = threadIdx.x;                 // 512 threads
    float wf = w_f0[d], we = w_en[d];
    float v0 = s_f0[d] * wf;
    float v1 = bi_f0[d] * wf;
    float v2 = s_en[d] * we;
    float v3 = bi_en[d] * we;
    g_swf0[d] = v0; g_swen[d] = v2;

    float v[4] = {v0, v1, v2, v3};
    int lane = d & 31, w = d >> 5;
#pragma unroll
    for (int j = 0; j < 4; j++) {
        float x = v[j];
#pragma unroll
        for (int o = 16; o > 0; o >>= 1) x += __shfl_xor_sync(0xffffffffu, x, o);
        if (lane == 0) red[j][w] = x;
    }
    __syncthreads();
    if (d < 4) {
        float s = 0.0f;
#pragma unroll
        for (int k = 0; k < 16; k++) s += red[d][k];
        g_hc[d] = s;
    }
}

// ---------------------------------------------------------------------------
// TF32 tensor-core GEMM: g_ht[b][d][t] = (X@W)[row=(b,t)][d] + bias[d] + freq[t][d]
// ---------------------------------------------------------------------------
#define AST 20
#define BST 20

__global__ __launch_bounds__(256)
void gemm_tf32_kernel(const float* __restrict__ X, const float* __restrict__ W,
                      const float* __restrict__ bias, const float* __restrict__ freq) {
    __shared__ __align__(16) unsigned char smem_raw[34048];
    uint32_t* As = (uint32_t*)smem_raw;
    uint32_t* Bs = (uint32_t*)(smem_raw + 20480);

    int tid = threadIdx.x;
    int lane = tid & 31, wid = tid >> 5;
    int warp_m = wid >> 1, warp_n = wid & 1;
    int rowBase = blockIdx.y * 128;
    int colBase = blockIdx.x * 64;

    float acc[2][4][4];
#pragma unroll
    for (int i = 0; i < 2; i++)
#pragma unroll
        for (int j = 0; j < 4; j++)
#pragma unroll
            for (int k = 0; k < 4; k++) acc[i][j][k] = 0.0f;

    int a_row = (lane & 7) + ((lane >> 3) & 1) * 8;
    int a_colw = (lane >> 4) * 4;
    const uint32_t* aPtr = As + (warp_m * 32 + a_row) * AST + a_colw;
    int b_row = (lane & 7) + ((lane >> 4) << 3);
    int b_colw = ((lane >> 3) & 1) * 4;
    const uint32_t* bPtr = Bs + (warp_n * 32 + b_row) * BST + b_colw;

    int arow = tid >> 2;
    int acol = (tid & 3) << 2;
    int bn   = tid & 63;
    int bk0  = (tid >> 6) << 2;

    const float* Xp = X + (size_t)rowBase * Ee;
    const float* Wp = W + colBase;

    {
        float4 va0 = *(const float4*)(Xp + (size_t)arow * Ee + acol);
        float4 va1 = *(const float4*)(Xp + (size_t)(arow + 64) * Ee + acol);
        uint4 ua0 = make_uint4(f2tf(va0.x), f2tf(va0.y), f2tf(va0.z), f2tf(va0.w));
        uint4 ua1 = make_uint4(f2tf(va1.x), f2tf(va1.y), f2tf(va1.z), f2tf(va1.w));
        *(uint4*)&As[arow * AST + acol] = ua0;
        *(uint4*)&As[(arow + 64) * AST + acol] = ua1;
        float b0 = Wp[(size_t)(bk0 + 0) * Dd + bn];
        float b1 = Wp[(size_t)(bk0 + 1) * Dd + bn];
        float b2 = Wp[(size_t)(bk0 + 2) * Dd + bn];
        float b3 = Wp[(size_t)(bk0 + 3) * Dd + bn];
        *(uint4*)&Bs[bn * BST + bk0] = make_uint4(f2tf(b0), f2tf(b1), f2tf(b2), f2tf(b3));
    }
    __syncthreads();

    int buf = 0;
    for (int kt = 16; kt < Ee; kt += 16) {
        float4 va0 = *(const float4*)(Xp + (size_t)arow * Ee + kt + acol);
        float4 va1 = *(const float4*)(Xp + (size_t)(arow + 64) * Ee + kt + acol);
        float pb0 = Wp[(size_t)(kt + bk0 + 0) * Dd + bn];
        float pb1 = Wp[(size_t)(kt + bk0 + 1) * Dd + bn];
        float pb2 = Wp[(size_t)(kt + bk0 + 2) * Dd + bn];
        float pb3 = Wp[(size_t)(kt + bk0 + 3) * Dd + bn];

        const uint32_t* aB = aPtr + buf * 2560;
        const uint32_t* bB = bPtr + buf * 1280;
#pragma unroll
        for (int k8 = 0; k8 < 2; k8++) {
            uint32_t a[2][4], bb[2][4];
            ldsm4(a[0][0], a[0][1], a[0][2], a[0][3], aB + k8 * 8);
            ldsm4(a[1][0], a[1][1], a[1][2], a[1][3], aB + 320 + k8 * 8);
            ldsm4(bb[0][0], bb[0][1], bb[0][2], bb[0][3], bB + k8 * 8);
            ldsm4(bb[1][0], bb[1][1], bb[1][2], bb[1][3], bB + 320 + k8 * 8);
#pragma unroll
            for (int mi = 0; mi < 2; mi++) {
                mma_tf32(acc[mi][0], a[mi], bb[0][0], bb[0][1]);
                mma_tf32(acc[mi][1], a[mi], bb[0][2], bb[0][3]);
                mma_tf32(acc[mi][2], a[mi], bb[1][0], bb[1][1]);
                mma_tf32(acc[mi][3], a[mi], bb[1][2], bb[1][3]);
            }
        }

        int nb = buf ^ 1;
        uint4 ua0 = make_uint4(f2tf(va0.x), f2tf(va0.y), f2tf(va0.z), f2tf(va0.w));
        uint4 ua1 = make_uint4(f2tf(va1.x), f2tf(va1.y), f2tf(va1.z), f2tf(va1.w));
        *(uint4*)&As[nb * 2560 + arow * AST + acol] = ua0;
        *(uint4*)&As[nb * 2560 + (arow + 64) * AST + acol] = ua1;
        *(uint4*)&Bs[nb * 1280 + bn * BST + bk0] =
            make_uint4(f2tf(pb0), f2tf(pb1), f2tf(pb2), f2tf(pb3));
        __syncthreads();
        buf = nb;
    }

    {
        const uint32_t* aB = aPtr + buf * 2560;
        const uint32_t* bB = bPtr + buf * 1280;
#pragma unroll
        for (int k8 = 0; k8 < 2; k8++) {
            uint32_t a[2][4], bb[2][4];
            ldsm4(a[0][0], a[0][1], a[0][2], a[0][3], aB + k8 * 8);
            ldsm4(a[1][0], a[1][1], a[1][2], a[1][3], aB + 320 + k8 * 8);
            ldsm4(bb[0][0], bb[0][1], bb[0][2], bb[0][3], bB + k8 * 8);
            ldsm4(bb[1][0], bb[1][1], bb[1][2], bb[1][3], bB + 320 + k8 * 8);
#pragma unroll
            for (int mi = 0; mi < 2; mi++) {
                mma_tf32(acc[mi][0], a[mi], bb[0][0], bb[0][1]);
                mma_tf32(acc[mi][1], a[mi], bb[0][2], bb[0][3]);
                mma_tf32(acc[mi][2], a[mi], bb[1][0], bb[1][1]);
                mma_tf32(acc[mi][3], a[mi], bb[1][2], bb[1][3]);
            }
        }
    }
    __syncthreads();

    float* SE = (float*)smem_raw;        // [64][132]
    int g = lane >> 2, tk = lane & 3;
#pragma unroll
    for (int mi = 0; mi < 2; mi++) {
#pragma unroll
        for (int ni = 0; ni < 4; ni++) {
            int rl = warp_m * 32 + mi * 16 + g;
            int cl = warp_n * 32 + ni * 8 + 2 * tk;
            int t0g = (rowBase + rl) & (Tt - 1);
            int t1g = (rowBase + rl + 8) & (Tt - 1);
            int c0 = colBase + cl, c1 = c0 + 1;
            SE[cl * 132 + rl]           = acc[mi][ni][0] + bias[c0] + freq[(size_t)t0g * Dd + c0];
            SE[(cl + 1) * 132 + rl]     = acc[mi][ni][1] + bias[c1] + freq[(size_t)t0g * Dd + c1];
            SE[cl * 132 + rl + 8]       = acc[mi][ni][2] + bias[c0] + freq[(size_t)t1g * Dd + c0];
            SE[(cl + 1) * 132 + rl + 8] = acc[mi][ni][3] + bias[c1] + freq[(size_t)t1g * Dd + c1];
        }
    }
    __syncthreads();

    int b = rowBase >> 11;
    int t0 = rowBase & (Tt - 1);
#pragma unroll
    for (int i = 0; i < 8; i++) {
        int idx = i * 256 + tid;
        int dr = idx >> 5;
        int w  = idx & 31;
        float4 v = *(float4*)&SE[dr * 132 + w * 4];
        *(float4*)&g_ht[((size_t)(b * Dd) + colBase + dr) * Tt + t0 + w * 4] = v;
    }
}

// ---------------------------------------------------------------------------
// Fused 4-layer S4 stack. Block = 128 thr (c 0..63, dl 0..1), 8 blocks/SM ->
// single wave over 1024 blocks. Layer 0 streams u from gmem; layer 3 streams
// the result back; middle layers keep u in swizzled smem.
// ---------------------------------------------------------------------------
__global__ __launch_bounds__(128, 8)
void s4_stack_kernel(const float* __restrict__ D_skip) {
    __shared__ float sx[NCH * SXS];     // 8.7 KB
    __shared__ float us[DBLK * Tt];     // 16 KB

    int tid  = threadIdx.x;
    int dl   = tid & 1;
    int c    = tid >> 1;
    int b    = blockIdx.x >> 8;
    int dblk = blockIdx.x & 255;
    int d    = dblk * DBLK + dl;
    int rot  = tid & 31;
    int chanbase = dl * Tt + c * TC;

    // phase-2 mapping
    int seg = tid & 3;                  // 0..3
    int dn  = tid >> 2;                 // 0..31
    int dl2 = dn >> 4, n2 = dn & 15;

    float4* gu = (float4*)(g_ht + ((size_t)(b * Dd) + d) * Tt + c * TC);

#pragma unroll 1
    for (int l = 0; l < Ll; l++) {
        ull a2[8];
        {
            const float4* ap4 = (const float4*)(g_Abar + (size_t)l * DN + d * Nn);
#pragma unroll
            for (int q = 0; q < 4; q++) {
                float4 v = ap4[q];
                a2[2*q]   = pack2(v.x, v.y);
                a2[2*q+1] = pack2(v.z, v.w);
            }
        }

        // Phase 1: chunk scan from zero (z-form)
        ull z2[8];
#pragma unroll
        for (int q = 0; q < 8; q++) z2[q] = 0ull;

        if (l == 0) {
            // stream u from gmem (contiguous per thread), seed smem
#pragma unroll
            for (int j = 0; j < 8; j++) {
                float4 v = gu[j];
                int i0 = j * 4;
                us[chanbase + ((i0 + 0) ^ rot)] = v.x;
                us[chanbase + ((i0 + 1) ^ rot)] = v.y;
                us[chanbase + ((i0 + 2) ^ rot)] = v.z;
                us[chanbase + ((i0 + 3) ^ rot)] = v.w;
                float uu[4] = {v.x, v.y, v.z, v.w};
#pragma unroll
                for (int k = 0; k < 4; k++) {
                    ull u2 = pack2(uu[k], uu[k]);
#pragma unroll
                    for (int q = 0; q < 8; q++)
                        z2[q] = fma2(a2[q], z2[q], u2);
                }
            }
        } else {
#pragma unroll
            for (int i = 0; i < TC; i++) {
                float uu = us[chanbase + (i ^ rot)];
                ull u2 = pack2(uu, uu);
#pragma unroll
                for (int q = 0; q < 8; q++)
                    z2[q] = fma2(a2[q], z2[q], u2);
            }
        }
        {
            ull* so = (ull*)(sx + c * SXS + dl * Nn);
#pragma unroll
            for (int q = 0; q < 8; q++) so[q] = z2[q];
        }
        __syncthreads();

        // Phase 2: shuffle scan across 64 chunks (4 segments of 16)
        {
            float ap = g_AbarP[(size_t)l * DN + (dblk * DBLK + dl2) * Nn + n2];
            float f[16];
#pragma unroll
            for (int j = 0; j < 16; j++)
                f[j] = sx[(seg * 16 + j) * SXS + dn];

            float F = 0.0f;
#pragma unroll
            for (int j = 0; j < 16; j++) F = fmaf(ap, F, f[j]);

            float p2 = ap * ap, p4 = p2 * p2, p8 = p4 * p4;
            float m  = p8 * p8;             // ap^16

            float Fp = __shfl_up_sync(0xffffffffu, F, 1, 4);
            float mp = __shfl_up_sync(0xffffffffu, m, 1, 4);
            if (seg >= 1) { F = fmaf(m, Fp, F); m *= mp; }
            Fp = __shfl_up_sync(0xffffffffu, F, 2, 4);
            mp = __shfl_up_sync(0xffffffffu, m, 2, 4);
            if (seg >= 2) { F = fmaf(m, Fp, F); m *= mp; }

            float carry = __shfl_up_sync(0xffffffffu, F, 1, 4);
            if (seg == 0) carry = 0.0f;

            float xs = carry;
#pragma unroll
            for (int j = 0; j < 16; j++) {
                sx[(seg * 16 + j) * SXS + dn] = xs;
                xs = fmaf(ap, xs, f[j]);
            }
        }
        __syncthreads();

        // Phase 3: re-scan + fused epilogue
        ull cb2[8];
        {
            const float4* cp4 = (const float4*)(g_CB + (size_t)l * DN + d * Nn);
#pragma unroll
            for (int q = 0; q < 4; q++) {
                float4 v = cp4[q];
                cb2[2*q]   = pack2(v.x, v.y);
                cb2[2*q+1] = pack2(v.z, v.w);
            }
        }
        float dsk = D_skip[l * Dd + d];

        {
            const ull* si = (const ull*)(sx + c * SXS + dl * Nn);
#pragma unroll
            for (int q = 0; q < 8; q++) z2[q] = si[q];
        }

        if (l < Ll - 1) {
#pragma unroll
            for (int i = 0; i < TC; i++) {
                float uu = us[chanbase + (i ^ rot)];
                ull u2 = pack2(uu, uu);
                ull y2 = 0ull;
#pragma unroll
                for (int q = 0; q < 8; q++) {
                    z2[q] = fma2(a2[q], z2[q], u2);
                    y2 = fma2(z2[q], cb2[q], y2);
                }
                float ylo, yhi; unpack2(y2, ylo, yhi);
                float y = ylo + yhi;
                y = fmaf(dsk, uu, y);
                float yy = y * y;
                float inner2 = 1.5957691216057308f * (y + 0.044715f * y * yy);
                float e = __expf(-inner2);
                float g = __fdividef(y, 1.0f + e);
                us[chanbase + (i ^ rot)] = uu + g;
            }
        } else {
            // last layer: write straight to gmem (contiguous per thread)
            float4 ob;
#pragma unroll
            for (int i = 0; i < TC; i++) {
                float uu = us[chanbase + (i ^ rot)];
                ull u2 = pack2(uu, uu);
                ull y2 = 0ull;
#pragma unroll
                for (int q = 0; q < 8; q++) {
                    z2[q] = fma2(a2[q], z2[q], u2);
                    y2 = fma2(z2[q], cb2[q], y2);
                }
                float ylo, yhi; unpack2(y2, ylo, yhi);
                float y = ylo + yhi;
                y = fmaf(dsk, uu, y);
                float yy = y * y;
                float inner2 = 1.5957691216057308f * (y + 0.044715f * y * yy);
                float e = __expf(-inner2);
                float g = __fdividef(y, 1.0f + e);
                float r = uu + g;
                int k = i & 3;
                if (k == 0) ob.x = r;
                else if (k == 1) ob.y = r;
                else if (k == 2) ob.z = r;
                else { ob.w = r; gu[i >> 2] = ob; }
            }
        }
        // No sync before next layer's phase 1: each thread re-reads only the
        // us/sx slots it itself wrote.
    }
}

// ---------------------------------------------------------------------------
// Head on transposed layout, single pass.
// ---------------------------------------------------------------------------
__global__ __launch_bounds__(256)
void head_kernel(const float* __restrict__ b_f0, const float* __restrict__ b_en,
                 float* __restrict__ out) {
    __shared__ float sh[8][4][32];
    int tid = threadIdx.x;
    int tt = tid & 31, oct = tid >> 5;
    int rowBase = blockIdx.x * 32;
    int b = rowBase >> 11, t0 = rowBase & (Tt - 1);

    const float* hp = g_ht + ((size_t)(b * Dd) + oct * 64) * Tt + t0 + tt;
    const float* swf = g_swf0 + oct * 64;
    const float* swe = g_swen + oct * 64;

    float s1 = 0.0f, s2 = 0.0f, sf = 0.0f, se = 0.0f;
#pragma unroll 8
    for (int dd = 0; dd < 64; dd++) {
        float v = hp[(size_t)dd * Tt];
        s1 += v;
        s2 = fmaf(v, v, s2);
        sf = fmaf(v, __ldg(swf + dd), sf);
        se = fmaf(v, __ldg(swe + dd), se);
    }
    sh[oct][0][tt] = s1; sh[oct][1][tt] = s2;
    sh[oct][2][tt] = sf; sh[oct][3][tt] = se;
    __syncthreads();

    if (tid < 32) {
        float a0 = 0.0f, a1 = 0.0f, a2 = 0.0f, a3 = 0.0f;
#pragma unroll
        for (int o = 0; o < 8; o++) {
            a0 += sh[o][0][tt]; a1 += sh[o][1][tt];
            a2 += sh[o][2][tt]; a3 += sh[o][3][tt];
        }
        float mu = a0 * (1.0f / Dd);
        float var = a1 * (1.0f / Dd) - mu * mu;
        float rstd = rsqrtf(var + 1e-5f);
        out[rowBase + tt]                   = rstd * (a2 - mu * g_hc[0]) + g_hc[1] + b_f0[0];
        out[(size_t)Bb * Tt + rowBase + tt] = rstd * (a3 - mu * g_hc[2]) + g_hc[3] + b_en[0];
    }
}

// ---------------------------------------------------------------------------
extern "C" void kernel_launch(void* const* d_in, const int* in_sizes, int n_in,
                              void* d_out, int out_size) {
    const float* text_emb = (const float*)d_in[0];
    const float* W_in     = (const float*)d_in[1];
    const float* b_in     = (const float*)d_in[2];
    const float* freq_pe  = (const float*)d_in[3];
    const float* A_log    = (const float*)d_in[4];
    const float* B_ssm    = (const float*)d_in[5];
    const float* C_ssm    = (const float*)d_in[6];
    const float* log_dt   = (const float*)d_in[7];
    const float* D_skip   = (const float*)d_in[8];
    const float* ln_f0_s  = (const float*)d_in[9];
    const float* ln_f0_b  = (const float*)d_in[10];
    const float* W_f0     = (const float*)d_in[11];
    const float* b_f0     = (const float*)d_in[12];
    const float* ln_en_s  = (const float*)d_in[13];
    const float* ln_en_b  = (const float*)d_in[14];
    const float* W_en     = (const float*)d_in[15];
    const float* b_en     = (const float*)d_in[16];
    float* out = (float*)d_out;

    precompute_kernel<<<(Ll * DN + 255) / 256, 256>>>(A_log, B_ssm, C_ssm, log_dt);
    head_prep_kernel<<<1, Dd>>>(ln_f0_s, ln_f0_b, W_f0, ln_en_s, ln_en_b, W_en);

    dim3 ggrid(Dd / 64, (Bb * Tt) / 128);
    gemm_tf32_kernel<<<ggrid, 256>>>(text_emb, W_in, b_in, freq_pe);

    s4_stack_kernel<<<Bb * (Dd / DBLK), 128>>>(D_skip);

    head_kernel<<<(Bb * Tt) / 32, 256>>>(b_f0, b_en, out);
}

// round 8
// speedup vs baseline: 1.0557x; 1.0557x over previous
#include <cuda_runtime.h>
#include <math.h>
#include <stdint.h>

// Problem constants
#define Bb   4
#define Tt   2048
#define Ee   512
#define Dd   512
#define Nn   16
#define Ll   4
#define TC   32              // chunk length (time steps per thread)
#define NCH  (Tt / TC)       // 64 chunks
#define DN   (Dd * Nn)       // 8192
#define DBLK 2               // d-channels per block in fused scan
#define SXS  34              // padded smem row stride (floats, even for ull)

typedef unsigned long long ull;

__device__ __forceinline__ ull pack2(float lo, float hi) {
    ull r; asm("mov.b64 %0, {%1,%2};" : "=l"(r) : "f"(lo), "f"(hi)); return r;
}
__device__ __forceinline__ void unpack2(ull v, float& lo, float& hi) {
    asm("mov.b64 {%0,%1}, %2;" : "=f"(lo), "=f"(hi) : "l"(v));
}
__device__ __forceinline__ ull fma2(ull a, ull b, ull c) {
    ull d; asm("fma.rn.f32x2 %0, %1, %2, %3;" : "=l"(d) : "l"(a), "l"(b), "l"(c));
    return d;
}
__device__ __forceinline__ uint32_t f2tf(float f) {
    uint32_t u; asm("cvt.rna.tf32.f32 %0, %1;" : "=r"(u) : "f"(f)); return u;
}
__device__ __forceinline__ void ldsm4(uint32_t& r0, uint32_t& r1, uint32_t& r2,
                                      uint32_t& r3, const uint32_t* p) {
    uint32_t a = (uint32_t)__cvta_generic_to_shared(p);
    asm volatile("ldmatrix.sync.aligned.m8n8.x4.shared.b16 {%0,%1,%2,%3}, [%4];"
                 : "=r"(r0), "=r"(r1), "=r"(r2), "=r"(r3) : "r"(a));
}
__device__ __forceinline__ void mma_tf32(float* c, const uint32_t* a,
                                         uint32_t b0, uint32_t b1) {
    asm volatile("mma.sync.aligned.m16n8k8.row.col.f32.tf32.tf32.f32 "
                 "{%0,%1,%2,%3}, {%4,%5,%6,%7}, {%8,%9}, {%0,%1,%2,%3};"
                 : "+f"(c[0]), "+f"(c[1]), "+f"(c[2]), "+f"(c[3])
                 : "r"(a[0]), "r"(a[1]), "r"(a[2]), "r"(a[3]), "r"(b0), "r"(b1));
}

// Scratch (static device globals; no runtime allocation)
__device__ float g_ht[(size_t)Bb * Dd * Tt];       // residual stream, TRANSPOSED [b][d][t]
__device__ float g_Abar [Ll * DN];
__device__ float g_CB   [Ll * DN];                 // C * Bbar
__device__ float g_AbarP[Ll * DN];                 // Abar^TC
__device__ float g_swf0[Dd], g_swen[Dd];           // scale*weight per head
__device__ float g_hc[4];                          // SWf0, BWf0, SWen, BWen

// ---------------------------------------------------------------------------
// Precompute per-layer SSM constants
// ---------------------------------------------------------------------------
__global__ void precompute_kernel(const float* __restrict__ A_log,
                                  const float* __restrict__ B_ssm,
                                  const float* __restrict__ C_ssm,
                                  const float* __restrict__ log_dt) {
    int idx = blockIdx.x * blockDim.x + threadIdx.x;
    if (idx >= Ll * DN) return;
    int l  = idx / DN;
    int dn = idx % DN;
    int d  = dn / Nn;
    float dt = expf(log_dt[l * Dd + d]);
    float A  = -expf(A_log[idx]);
    float dA = dt * A;
    float ab = expf(dA);
    g_Abar [idx] = ab;
    g_CB   [idx] = (ab - 1.0f) / A * B_ssm[idx] * C_ssm[idx];
    g_AbarP[idx] = expf(dA * (float)TC);
}

// ---------------------------------------------------------------------------
// Head precompute
// ---------------------------------------------------------------------------
__global__ void head_prep_kernel(const float* __restrict__ s_f0, const float* __restrict__ bi_f0,
                                 const float* __restrict__ w_f0,
                                 const float* __restrict__ s_en, const float* __restrict__ bi_en,
                                 const float* __restrict__ w_en) {
    __shared__ float red[4][16];
    int d = threadIdx.x;                 // 512 threads
    float wf = w_f0[d], we = w_en[d];
    float v0 = s_f0[d] * wf;
    float v1 = bi_f0[d] * wf;
    float v2 = s_en[d] * we;
    float v3 = bi_en[d] * we;
    g_swf0[d] = v0; g_swen[d] = v2;

    float v[4] = {v0, v1, v2, v3};
    int lane = d & 31, w = d >> 5;
#pragma unroll
    for (int j = 0; j < 4; j++) {
        float x = v[j];
#pragma unroll
        for (int o = 16; o > 0; o >>= 1) x += __shfl_xor_sync(0xffffffffu, x, o);
        if (lane == 0) red[j][w] = x;
    }
    __syncthreads();
    if (d < 4) {
        float s = 0.0f;
#pragma unroll
        for (int k = 0; k < 16; k++) s += red[d][k];
        g_hc[d] = s;
    }
}

// ---------------------------------------------------------------------------
// TF32 tensor-core GEMM: g_ht[b][d][t] = (X@W)[row=(b,t)][d] + bias[d] + freq[t][d]
// ---------------------------------------------------------------------------
#define AST 20
#define BST 20

__global__ __launch_bounds__(256)
void gemm_tf32_kernel(const float* __restrict__ X, const float* __restrict__ W,
                      const float* __restrict__ bias, const float* __restrict__ freq) {
    __shared__ __align__(16) unsigned char smem_raw[34048];
    uint32_t* As = (uint32_t*)smem_raw;
    uint32_t* Bs = (uint32_t*)(smem_raw + 20480);

    int tid = threadIdx.x;
    int lane = tid & 31, wid = tid >> 5;
    int warp_m = wid >> 1, warp_n = wid & 1;
    int rowBase = blockIdx.y * 128;
    int colBase = blockIdx.x * 64;

    float acc[2][4][4];
#pragma unroll
    for (int i = 0; i < 2; i++)
#pragma unroll
        for (int j = 0; j < 4; j++)
#pragma unroll
            for (int k = 0; k < 4; k++) acc[i][j][k] = 0.0f;

    int a_row = (lane & 7) + ((lane >> 3) & 1) * 8;
    int a_colw = (lane >> 4) * 4;
    const uint32_t* aPtr = As + (warp_m * 32 + a_row) * AST + a_colw;
    int b_row = (lane & 7) + ((lane >> 4) << 3);
    int b_colw = ((lane >> 3) & 1) * 4;
    const uint32_t* bPtr = Bs + (warp_n * 32 + b_row) * BST + b_colw;

    int arow = tid >> 2;
    int acol = (tid & 3) << 2;
    int bn   = tid & 63;
    int bk0  = (tid >> 6) << 2;

    const float* Xp = X + (size_t)rowBase * Ee;
    const float* Wp = W + colBase;

    {
        float4 va0 = *(const float4*)(Xp + (size_t)arow * Ee + acol);
        float4 va1 = *(const float4*)(Xp + (size_t)(arow + 64) * Ee + acol);
        uint4 ua0 = make_uint4(f2tf(va0.x), f2tf(va0.y), f2tf(va0.z), f2tf(va0.w));
        uint4 ua1 = make_uint4(f2tf(va1.x), f2tf(va1.y), f2tf(va1.z), f2tf(va1.w));
        *(uint4*)&As[arow * AST + acol] = ua0;
        *(uint4*)&As[(arow + 64) * AST + acol] = ua1;
        float b0 = Wp[(size_t)(bk0 + 0) * Dd + bn];
        float b1 = Wp[(size_t)(bk0 + 1) * Dd + bn];
        float b2 = Wp[(size_t)(bk0 + 2) * Dd + bn];
        float b3 = Wp[(size_t)(bk0 + 3) * Dd + bn];
        *(uint4*)&Bs[bn * BST + bk0] = make_uint4(f2tf(b0), f2tf(b1), f2tf(b2), f2tf(b3));
    }
    __syncthreads();

    int buf = 0;
    for (int kt = 16; kt < Ee; kt += 16) {
        float4 va0 = *(const float4*)(Xp + (size_t)arow * Ee + kt + acol);
        float4 va1 = *(const float4*)(Xp + (size_t)(arow + 64) * Ee + kt + acol);
        float pb0 = Wp[(size_t)(kt + bk0 + 0) * Dd + bn];
        float pb1 = Wp[(size_t)(kt + bk0 + 1) * Dd + bn];
        float pb2 = Wp[(size_t)(kt + bk0 + 2) * Dd + bn];
        float pb3 = Wp[(size_t)(kt + bk0 + 3) * Dd + bn];

        const uint32_t* aB = aPtr + buf * 2560;
        const uint32_t* bB = bPtr + buf * 1280;
#pragma unroll
        for (int k8 = 0; k8 < 2; k8++) {
            uint32_t a[2][4], bb[2][4];
            ldsm4(a[0][0], a[0][1], a[0][2], a[0][3], aB + k8 * 8);
            ldsm4(a[1][0], a[1][1], a[1][2], a[1][3], aB + 320 + k8 * 8);
            ldsm4(bb[0][0], bb[0][1], bb[0][2], bb[0][3], bB + k8 * 8);
            ldsm4(bb[1][0], bb[1][1], bb[1][2], bb[1][3], bB + 320 + k8 * 8);
#pragma unroll
            for (int mi = 0; mi < 2; mi++) {
                mma_tf32(acc[mi][0], a[mi], bb[0][0], bb[0][1]);
                mma_tf32(acc[mi][1], a[mi], bb[0][2], bb[0][3]);
                mma_tf32(acc[mi][2], a[mi], bb[1][0], bb[1][1]);
                mma_tf32(acc[mi][3], a[mi], bb[1][2], bb[1][3]);
            }
        }

        int nb = buf ^ 1;
        uint4 ua0 = make_uint4(f2tf(va0.x), f2tf(va0.y), f2tf(va0.z), f2tf(va0.w));
        uint4 ua1 = make_uint4(f2tf(va1.x), f2tf(va1.y), f2tf(va1.z), f2tf(va1.w));
        *(uint4*)&As[nb * 2560 + arow * AST + acol] = ua0;
        *(uint4*)&As[nb * 2560 + (arow + 64) * AST + acol] = ua1;
        *(uint4*)&Bs[nb * 1280 + bn * BST + bk0] =
            make_uint4(f2tf(pb0), f2tf(pb1), f2tf(pb2), f2tf(pb3));
        __syncthreads();
        buf = nb;
    }

    {
        const uint32_t* aB = aPtr + buf * 2560;
        const uint32_t* bB = bPtr + buf * 1280;
#pragma unroll
        for (int k8 = 0; k8 < 2; k8++) {
            uint32_t a[2][4], bb[2][4];
            ldsm4(a[0][0], a[0][1], a[0][2], a[0][3], aB + k8 * 8);
            ldsm4(a[1][0], a[1][1], a[1][2], a[1][3], aB + 320 + k8 * 8);
            ldsm4(bb[0][0], bb[0][1], bb[0][2], bb[0][3], bB + k8 * 8);
            ldsm4(bb[1][0], bb[1][1], bb[1][2], bb[1][3], bB + 320 + k8 * 8);
#pragma unroll
            for (int mi = 0; mi < 2; mi++) {
                mma_tf32(acc[mi][0], a[mi], bb[0][0], bb[0][1]);
                mma_tf32(acc[mi][1], a[mi], bb[0][2], bb[0][3]);
                mma_tf32(acc[mi][2], a[mi], bb[1][0], bb[1][1]);
                mma_tf32(acc[mi][3], a[mi], bb[1][2], bb[1][3]);
            }
        }
    }
    __syncthreads();

    float* SE = (float*)smem_raw;        // [64][132]
    int g = lane >> 2, tk = lane & 3;
#pragma unroll
    for (int mi = 0; mi < 2; mi++) {
#pragma unroll
        for (int ni = 0; ni < 4; ni++) {
            int rl = warp_m * 32 + mi * 16 + g;
            int cl = warp_n * 32 + ni * 8 + 2 * tk;
            int t0g = (rowBase + rl) & (Tt - 1);
            int t1g = (rowBase + rl + 8) & (Tt - 1);
            int c0 = colBase + cl, c1 = c0 + 1;
            SE[cl * 132 + rl]           = acc[mi][ni][0] + bias[c0] + freq[(size_t)t0g * Dd + c0];
            SE[(cl + 1) * 132 + rl]     = acc[mi][ni][1] + bias[c1] + freq[(size_t)t0g * Dd + c1];
            SE[cl * 132 + rl + 8]       = acc[mi][ni][2] + bias[c0] + freq[(size_t)t1g * Dd + c0];
            SE[(cl + 1) * 132 + rl + 8] = acc[mi][ni][3] + bias[c1] + freq[(size_t)t1g * Dd + c1];
        }
    }
    __syncthreads();

    int b = rowBase >> 11;
    int t0 = rowBase & (Tt - 1);
#pragma unroll
    for (int i = 0; i < 8; i++) {
        int idx = i * 256 + tid;
        int dr = idx >> 5;
        int w  = idx & 31;
        float4 v = *(float4*)&SE[dr * 132 + w * 4];
        *(float4*)&g_ht[((size_t)(b * Dd) + colBase + dr) * Tt + t0 + w * 4] = v;
    }
}

// ---------------------------------------------------------------------------
// Fused 4-layer S4 stack. Block = 128 thr (c 0..63, dl 0..1).
// Coalesced cooperative gmem load/store; u in swizzled smem across layers.
// launch_bounds(128,7): regs<=73 -> 7 blocks/SM -> single wave over 1024 blocks.
// ---------------------------------------------------------------------------
__global__ __launch_bounds__(128, 7)
void s4_stack_kernel(const float* __restrict__ D_skip) {
    __shared__ float sx[NCH * SXS];     // 8.7 KB
    __shared__ float us[DBLK * Tt];     // 16 KB

    int tid  = threadIdx.x;
    int dl   = tid & 1;
    int c    = tid >> 1;
    int b    = blockIdx.x >> 8;
    int dblk = blockIdx.x & 255;
    int d    = dblk * DBLK + dl;
    int rot  = tid & 31;
    int chanbase = dl * Tt + c * TC;

    // phase-2 mapping
    int seg = tid & 3;                  // 0..3
    int dn  = tid >> 2;                 // 0..31
    int dl2 = dn >> 4, n2 = dn & 15;

    // Cooperative coalesced load: 2 channels x 2048 floats -> swizzled us
    const float4* gb4 = (const float4*)(g_ht + ((size_t)(b * Dd) + dblk * DBLK) * Tt);
#pragma unroll
    for (int j = 0; j < 8; j++) {
        int p = j * 128 + tid;          // 0..1023 float4
        float4 v = gb4[p];
        int ch = p >> 9;
        int t  = (p & 511) << 2;
        int base = ch * Tt + (t & ~31);
        int rr = (((t >> 5) << 1) + ch) & 31;
        int i0 = t & 31;
        us[base + ((i0 + 0) ^ rr)] = v.x;
        us[base + ((i0 + 1) ^ rr)] = v.y;
        us[base + ((i0 + 2) ^ rr)] = v.z;
        us[base + ((i0 + 3) ^ rr)] = v.w;
    }
    __syncthreads();

#pragma unroll 1
    for (int l = 0; l < Ll; l++) {
        ull a2[8];
        {
            const float4* ap4 = (const float4*)(g_Abar + (size_t)l * DN + d * Nn);
#pragma unroll
            for (int q = 0; q < 4; q++) {
                float4 v = ap4[q];
                a2[2*q]   = pack2(v.x, v.y);
                a2[2*q+1] = pack2(v.z, v.w);
            }
        }

        // Phase 1: chunk scan from zero (z-form)
        ull z2[8];
#pragma unroll
        for (int q = 0; q < 8; q++) z2[q] = 0ull;
#pragma unroll
        for (int i = 0; i < TC; i++) {
            float uu = us[chanbase + (i ^ rot)];
            ull u2 = pack2(uu, uu);
#pragma unroll
            for (int q = 0; q < 8; q++)
                z2[q] = fma2(a2[q], z2[q], u2);
        }
        {
            ull* so = (ull*)(sx + c * SXS + dl * Nn);
#pragma unroll
            for (int q = 0; q < 8; q++) so[q] = z2[q];
        }
        __syncthreads();

        // Phase 2: two-pass shuffle scan across 64 chunks (4 segments of 16)
        // (two passes over smem avoid a 16-register f[] array)
        {
            float ap = g_AbarP[(size_t)l * DN + (dblk * DBLK + dl2) * Nn + n2];

            // pass A: segment reduction F = sum_j ap^(15-j) f_j
            float F = 0.0f;
#pragma unroll
            for (int j = 0; j < 16; j++)
                F = fmaf(ap, F, sx[(seg * 16 + j) * SXS + dn]);

            float p2 = ap * ap, p4 = p2 * p2, p8 = p4 * p4;
            float m  = p8 * p8;             // ap^16

            float Fp = __shfl_up_sync(0xffffffffu, F, 1, 4);
            float mp = __shfl_up_sync(0xffffffffu, m, 1, 4);
            if (seg >= 1) { F = fmaf(m, Fp, F); m *= mp; }
            Fp = __shfl_up_sync(0xffffffffu, F, 2, 4);
            mp = __shfl_up_sync(0xffffffffu, m, 2, 4);
            if (seg >= 2) { F = fmaf(m, Fp, F); m *= mp; }

            float carry = __shfl_up_sync(0xffffffffu, F, 1, 4);
            if (seg == 0) carry = 0.0f;

            // pass B: rescan with rolling 2-deep buffer
            float xs = carry;
            float fcur = sx[(seg * 16) * SXS + dn];
#pragma unroll
            for (int j = 0; j < 16; j++) {
                float fnext = (j < 15) ? sx[(seg * 16 + j + 1) * SXS + dn] : 0.0f;
                sx[(seg * 16 + j) * SXS + dn] = xs;
                xs = fmaf(ap, xs, fcur);
                fcur = fnext;
            }
        }
        __syncthreads();

        // Phase 3: re-scan + fused epilogue
        ull cb2[8];
        {
            const float4* cp4 = (const float4*)(g_CB + (size_t)l * DN + d * Nn);
#pragma unroll
            for (int q = 0; q < 4; q++) {
                float4 v = cp4[q];
                cb2[2*q]   = pack2(v.x, v.y);
                cb2[2*q+1] = pack2(v.z, v.w);
            }
        }
        float dsk = D_skip[l * Dd + d];

        {
            const ull* si = (const ull*)(sx + c * SXS + dl * Nn);
#pragma unroll
            for (int q = 0; q < 8; q++) z2[q] = si[q];
        }

#pragma unroll
        for (int i = 0; i < TC; i++) {
            float uu = us[chanbase + (i ^ rot)];
            ull u2 = pack2(uu, uu);
            ull y2 = 0ull;
#pragma unroll
            for (int q = 0; q < 8; q++) {
                z2[q] = fma2(a2[q], z2[q], u2);
                y2 = fma2(z2[q], cb2[q], y2);
            }
            float ylo, yhi; unpack2(y2, ylo, yhi);
            float y = ylo + yhi;
            y = fmaf(dsk, uu, y);
            float yy = y * y;
            float inner2 = 1.5957691216057308f * (y + 0.044715f * y * yy);
            float e = __expf(-inner2);
            float g = __fdividef(y, 1.0f + e);
            us[chanbase + (i ^ rot)] = uu + g;
        }
        // No sync before next layer's phase 1: each thread re-reads only the
        // us/sx slots it itself wrote.
    }
    __syncthreads();

    // Cooperative coalesced writeback (reverse swizzle)
    float4* gb4o = (float4*)(g_ht + ((size_t)(b * Dd) + dblk * DBLK) * Tt);
#pragma unroll
    for (int j = 0; j < 8; j++) {
        int p = j * 128 + tid;
        int ch = p >> 9;
        int t  = (p & 511) << 2;
        int base = ch * Tt + (t & ~31);
        int rr = (((t >> 5) << 1) + ch) & 31;
        int i0 = t & 31;
        float4 v;
        v.x = us[base + ((i0 + 0) ^ rr)];
        v.y = us[base + ((i0 + 1) ^ rr)];
        v.z = us[base + ((i0 + 2) ^ rr)];
        v.w = us[base + ((i0 + 3) ^ rr)];
        gb4o[p] = v;
    }
}

// ---------------------------------------------------------------------------
// Head on transposed layout, single pass.
// ---------------------------------------------------------------------------
__global__ __launch_bounds__(256)
void head_kernel(const float* __restrict__ b_f0, const float* __restrict__ b_en,
                 float* __restrict__ out) {
    __shared__ float sh[8][4][32];
    int tid = threadIdx.x;
    int tt = tid & 31, oct = tid >> 5;
    int rowBase = blockIdx.x * 32;
    int b = rowBase >> 11, t0 = rowBase & (Tt - 1);

    const float* hp = g_ht + ((size_t)(b * Dd) + oct * 64) * Tt + t0 + tt;
    const float* swf = g_swf0 + oct * 64;
    const float* swe = g_swen + oct * 64;

    float s1 = 0.0f, s2 = 0.0f, sf = 0.0f, se = 0.0f;
#pragma unroll 8
    for (int dd = 0; dd < 64; dd++) {
        float v = hp[(size_t)dd * Tt];
        s1 += v;
        s2 = fmaf(v, v, s2);
        sf = fmaf(v, __ldg(swf + dd), sf);
        se = fmaf(v, __ldg(swe + dd), se);
    }
    sh[oct][0][tt] = s1; sh[oct][1][tt] = s2;
    sh[oct][2][tt] = sf; sh[oct][3][tt] = se;
    __syncthreads();

    if (tid < 32) {
        float a0 = 0.0f, a1 = 0.0f, a2 = 0.0f, a3 = 0.0f;
#pragma unroll
        for (int o = 0; o < 8; o++) {
            a0 += sh[o][0][tt]; a1 += sh[o][1][tt];
            a2 += sh[o][2][tt]; a3 += sh[o][3][tt];
        }
        float mu = a0 * (1.0f / Dd);
        float var = a1 * (1.0f / Dd) - mu * mu;
        float rstd = rsqrtf(var + 1e-5f);
        out[rowBase + tt]                   = rstd * (a2 - mu * g_hc[0]) + g_hc[1] + b_f0[0];
        out[(size_t)Bb * Tt + rowBase + tt] = rstd * (a3 - mu * g_hc[2]) + g_hc[3] + b_en[0];
    }
}

// ---------------------------------------------------------------------------
extern "C" void kernel_launch(void* const* d_in, const int* in_sizes, int n_in,
                              void* d_out, int out_size) {
    const float* text_emb = (const float*)d_in[0];
    const float* W_in     = (const float*)d_in[1];
    const float* b_in     = (const float*)d_in[2];
    const float* freq_pe  = (const float*)d_in[3];
    const float* A_log    = (const float*)d_in[4];
    const float* B_ssm    = (const float*)d_in[5];
    const float* C_ssm    = (const float*)d_in[6];
    const float* log_dt   = (const float*)d_in[7];
    const float* D_skip   = (const float*)d_in[8];
    const float* ln_f0_s  = (const float*)d_in[9];
    const float* ln_f0_b  = (const float*)d_in[10];
    const float* W_f0     = (const float*)d_in[11];
    const float* b_f0     = (const float*)d_in[12];
    const float* ln_en_s  = (const float*)d_in[13];
    const float* ln_en_b  = (const float*)d_in[14];
    const float* W_en     = (const float*)d_in[15];
    const float* b_en     = (const float*)d_in[16];
    float* out = (float*)d_out;

    precompute_kernel<<<(Ll * DN + 255) / 256, 256>>>(A_log, B_ssm, C_ssm, log_dt);
    head_prep_kernel<<<1, Dd>>>(ln_f0_s, ln_f0_b, W_f0, ln_en_s, ln_en_b, W_en);

    dim3 ggrid(Dd / 64, (Bb * Tt) / 128);
    gemm_tf32_kernel<<<ggrid, 256>>>(text_emb, W_in, b_in, freq_pe);

    s4_stack_kernel<<<Bb * (Dd / DBLK), 128>>>(D_skip);

    head_kernel<<<(Bb * Tt) / 32, 256>>>(b_f0, b_en, out);
}

// round 9
// speedup vs baseline: 1.1659x; 1.1043x over previous
#include <cuda_runtime.h>
#include <math.h>
#include <stdint.h>

// Problem constants
#define Bb   4
#define Tt   2048
#define Ee   512
#define Dd   512
#define Nn   16
#define Ll   4
#define TC   32              // chunk length (time steps per thread)
#define NCH  (Tt / TC)       // 64 chunks
#define DN   (Dd * Nn)       // 8192
#define DBLK 2               // d-channels per block in fused scan
#define SXS  34              // padded smem row stride (floats, even for ull)

typedef unsigned long long ull;

__device__ __forceinline__ ull pack2(float lo, float hi) {
    ull r; asm("mov.b64 %0, {%1,%2};" : "=l"(r) : "f"(lo), "f"(hi)); return r;
}
__device__ __forceinline__ void unpack2(ull v, float& lo, float& hi) {
    asm("mov.b64 {%0,%1}, %2;" : "=f"(lo), "=f"(hi) : "l"(v));
}
__device__ __forceinline__ ull fma2(ull a, ull b, ull c) {
    ull d; asm("fma.rn.f32x2 %0, %1, %2, %3;" : "=l"(d) : "l"(a), "l"(b), "l"(c));
    return d;
}
__device__ __forceinline__ uint32_t f2tf(float f) {
    uint32_t u; asm("cvt.rna.tf32.f32 %0, %1;" : "=r"(u) : "f"(f)); return u;
}
__device__ __forceinline__ void ldsm4(uint32_t& r0, uint32_t& r1, uint32_t& r2,
                                      uint32_t& r3, const uint32_t* p) {
    uint32_t a = (uint32_t)__cvta_generic_to_shared(p);
    asm volatile("ldmatrix.sync.aligned.m8n8.x4.shared.b16 {%0,%1,%2,%3}, [%4];"
                 : "=r"(r0), "=r"(r1), "=r"(r2), "=r"(r3) : "r"(a));
}
__device__ __forceinline__ void mma_tf32(float* c, const uint32_t* a,
                                         uint32_t b0, uint32_t b1) {
    asm volatile("mma.sync.aligned.m16n8k8.row.col.f32.tf32.tf32.f32 "
                 "{%0,%1,%2,%3}, {%4,%5,%6,%7}, {%8,%9}, {%0,%1,%2,%3};"
                 : "+f"(c[0]), "+f"(c[1]), "+f"(c[2]), "+f"(c[3])
                 : "r"(a[0]), "r"(a[1]), "r"(a[2]), "r"(a[3]), "r"(b0), "r"(b1));
}

// Scratch (static device globals; no runtime allocation)
__device__ float g_ht[(size_t)Bb * Dd * Tt];       // residual stream, TRANSPOSED [b][d][t]
__device__ uint32_t g_Wt[(size_t)Dd * Ee];         // W transposed, tf32 [d][e]
__device__ float g_Abar [Ll * DN];
__device__ float g_CB   [Ll * DN];                 // C * Bbar
__device__ float g_AbarP[Ll * DN];                 // Abar^TC
__device__ float g_swf0[Dd], g_swen[Dd];           // scale*weight per head
__device__ float g_hc[4];                          // SWf0, BWf0, SWen, BWen

// ---------------------------------------------------------------------------
// Precompute per-layer SSM constants
// ---------------------------------------------------------------------------
__global__ void precompute_kernel(const float* __restrict__ A_log,
                                  const float* __restrict__ B_ssm,
                                  const float* __restrict__ C_ssm,
                                  const float* __restrict__ log_dt) {
    int idx = blockIdx.x * blockDim.x + threadIdx.x;
    if (idx >= Ll * DN) return;
    int l  = idx / DN;
    int dn = idx % DN;
    int d  = dn / Nn;
    float dt = expf(log_dt[l * Dd + d]);
    float A  = -expf(A_log[idx]);
    float dA = dt * A;
    float ab = expf(dA);
    g_Abar [idx] = ab;
    g_CB   [idx] = (ab - 1.0f) / A * B_ssm[idx] * C_ssm[idx];
    g_AbarP[idx] = expf(dA * (float)TC);
}

// ---------------------------------------------------------------------------
// W transpose + tf32 convert: g_Wt[d][e] = tf32(W[e][d])
// ---------------------------------------------------------------------------
__global__ void wt_prep_kernel(const float* __restrict__ W) {
    __shared__ float tile[32][33];
    int tx = threadIdx.x, ty = threadIdx.y;     // (32, 8)
    int d0 = blockIdx.x * 32, e0 = blockIdx.y * 32;
#pragma unroll
    for (int j = 0; j < 4; j++)
        tile[ty + j * 8][tx] = W[(size_t)(e0 + ty + j * 8) * Dd + d0 + tx];
    __syncthreads();
#pragma unroll
    for (int j = 0; j < 4; j++)
        g_Wt[(size_t)(d0 + ty + j * 8) * Ee + e0 + tx] = f2tf(tile[tx][ty + j * 8]);
}

// ---------------------------------------------------------------------------
// Head precompute
// ---------------------------------------------------------------------------
__global__ void head_prep_kernel(const float* __restrict__ s_f0, const float* __restrict__ bi_f0,
                                 const float* __restrict__ w_f0,
                                 const float* __restrict__ s_en, const float* __restrict__ bi_en,
                                 const float* __restrict__ w_en) {
    __shared__ float red[4][16];
    int d = threadIdx.x;                 // 512 threads
    float wf = w_f0[d], we = w_en[d];
    float v0 = s_f0[d] * wf;
    float v1 = bi_f0[d] * wf;
    float v2 = s_en[d] * we;
    float v3 = bi_en[d] * we;
    g_swf0[d] = v0; g_swen[d] = v2;

    float v[4] = {v0, v1, v2, v3};
    int lane = d & 31, w = d >> 5;
#pragma unroll
    for (int j = 0; j < 4; j++) {
        float x = v[j];
#pragma unroll
        for (int o = 16; o > 0; o >>= 1) x += __shfl_xor_sync(0xffffffffu, x, o);
        if (lane == 0) red[j][w] = x;
    }
    __syncthreads();
    if (d < 4) {
        float s = 0.0f;
#pragma unroll
        for (int k = 0; k < 16; k++) s += red[d][k];
        g_hc[d] = s;
    }
}

// ---------------------------------------------------------------------------
// TF32 GEMM, 128x128x16 tiles: g_ht[b][d][t] = (X@W)[b,t][d] + bias[d] + freq[t][d]
// 256 threads = 8 warps (2 warp_m x 4 warp_n), warp tile 64x32.
// A from X (cvt in-flight), B from pre-converted g_Wt. Double-buffered smem.
// ---------------------------------------------------------------------------
#define AST 20     // smem row stride (words)
#define BUFW 2560  // words per buffer (128 rows * 20)

__global__ __launch_bounds__(256)
void gemm_tf32_kernel(const float* __restrict__ X,
                      const float* __restrict__ bias, const float* __restrict__ freq) {
    __shared__ __align__(16) uint32_t smem[4 * BUFW];   // As[2] then Bs[2] = 40960 B
    uint32_t* As = smem;
    uint32_t* Bs = smem + 2 * BUFW;

    int tid = threadIdx.x;
    int lane = tid & 31, wid = tid >> 5;
    int warp_m = wid >> 2, warp_n = wid & 3;
    int rowBase = blockIdx.y * 128;      // t rows
    int colBase = blockIdx.x * 128;      // d cols

    float acc[4][4][4];
#pragma unroll
    for (int i = 0; i < 4; i++)
#pragma unroll
        for (int j = 0; j < 4; j++)
#pragma unroll
            for (int k = 0; k < 4; k++) acc[i][j][k] = 0.0f;

    // ldmatrix per-lane addressing (validated pattern)
    int a_row = (lane & 7) + ((lane >> 3) & 1) * 8;
    int a_colw = (lane >> 4) * 4;
    const uint32_t* aPtr = As + (warp_m * 64 + a_row) * AST + a_colw;
    int b_row = (lane & 7) + ((lane >> 4) << 3);
    int b_colw = ((lane >> 3) & 1) * 4;
    const uint32_t* bPtr = Bs + (warp_n * 32 + b_row) * AST + b_colw;

    // gmem->smem mapping (both A and B tiles are 128 rows x 16 floats)
    int frow = tid >> 2;                 // 0..63 (and +64)
    int fcol = (tid & 3) << 2;           // word 0,4,8,12

    const float* Xp = X + (size_t)rowBase * Ee;
    const uint32_t* Wp = g_Wt + (size_t)colBase * Ee;

    // prologue: ktile 0 -> buf 0
    {
        float4 va0 = *(const float4*)(Xp + (size_t)frow * Ee + fcol);
        float4 va1 = *(const float4*)(Xp + (size_t)(frow + 64) * Ee + fcol);
        *(uint4*)&As[frow * AST + fcol] =
            make_uint4(f2tf(va0.x), f2tf(va0.y), f2tf(va0.z), f2tf(va0.w));
        *(uint4*)&As[(frow + 64) * AST + fcol] =
            make_uint4(f2tf(va1.x), f2tf(va1.y), f2tf(va1.z), f2tf(va1.w));
        *(uint4*)&Bs[frow * AST + fcol] = *(const uint4*)(Wp + (size_t)frow * Ee + fcol);
        *(uint4*)&Bs[(frow + 64) * AST + fcol] = *(const uint4*)(Wp + (size_t)(frow + 64) * Ee + fcol);
    }
    __syncthreads();

    int buf = 0;
    for (int kt = 16; kt < Ee; kt += 16) {
        // prefetch next ktile
        float4 va0 = *(const float4*)(Xp + (size_t)frow * Ee + kt + fcol);
        float4 va1 = *(const float4*)(Xp + (size_t)(frow + 64) * Ee + kt + fcol);
        uint4 ub0 = *(const uint4*)(Wp + (size_t)frow * Ee + kt + fcol);
        uint4 ub1 = *(const uint4*)(Wp + (size_t)(frow + 64) * Ee + kt + fcol);

        // compute current buffer
        const uint32_t* aB = aPtr + buf * BUFW;
        const uint32_t* bB = bPtr + buf * BUFW;
#pragma unroll
        for (int k8 = 0; k8 < 2; k8++) {
            uint32_t a[4][4], bb[2][4];
#pragma unroll
            for (int mi = 0; mi < 4; mi++)
                ldsm4(a[mi][0], a[mi][1], a[mi][2], a[mi][3], aB + mi * (16 * AST) + k8 * 8);
#pragma unroll
            for (int nj = 0; nj < 2; nj++)
                ldsm4(bb[nj][0], bb[nj][1], bb[nj][2], bb[nj][3], bB + nj * (16 * AST) + k8 * 8);
#pragma unroll
            for (int mi = 0; mi < 4; mi++) {
#pragma unroll
                for (int nj = 0; nj < 2; nj++) {
                    mma_tf32(acc[mi][2 * nj + 0], a[mi], bb[nj][0], bb[nj][1]);
                    mma_tf32(acc[mi][2 * nj + 1], a[mi], bb[nj][2], bb[nj][3]);
                }
            }
        }

        // store prefetched tile
        int nb = buf ^ 1;
        *(uint4*)&As[nb * BUFW + frow * AST + fcol] =
            make_uint4(f2tf(va0.x), f2tf(va0.y), f2tf(va0.z), f2tf(va0.w));
        *(uint4*)&As[nb * BUFW + (frow + 64) * AST + fcol] =
            make_uint4(f2tf(va1.x), f2tf(va1.y), f2tf(va1.z), f2tf(va1.w));
        *(uint4*)&Bs[nb * BUFW + frow * AST + fcol] = ub0;
        *(uint4*)&Bs[nb * BUFW + (frow + 64) * AST + fcol] = ub1;
        __syncthreads();
        buf = nb;
    }

    // last ktile
    {
        const uint32_t* aB = aPtr + buf * BUFW;
        const uint32_t* bB = bPtr + buf * BUFW;
#pragma unroll
        for (int k8 = 0; k8 < 2; k8++) {
            uint32_t a[4][4], bb[2][4];
#pragma unroll
            for (int mi = 0; mi < 4; mi++)
                ldsm4(a[mi][0], a[mi][1], a[mi][2], a[mi][3], aB + mi * (16 * AST) + k8 * 8);
#pragma unroll
            for (int nj = 0; nj < 2; nj++)
                ldsm4(bb[nj][0], bb[nj][1], bb[nj][2], bb[nj][3], bB + nj * (16 * AST) + k8 * 8);
#pragma unroll
            for (int mi = 0; mi < 4; mi++) {
#pragma unroll
                for (int nj = 0; nj < 2; nj++) {
                    mma_tf32(acc[mi][2 * nj + 0], a[mi], bb[nj][0], bb[nj][1]);
                    mma_tf32(acc[mi][2 * nj + 1], a[mi], bb[nj][2], bb[nj][3]);
                }
            }
        }
    }
    __syncthreads();

    // Epilogue: two passes of 64 d-columns through smem transpose
    float* SE = (float*)smem;            // [64][132] floats = 33792 B
    int g = lane >> 2, tk = lane & 3;
    int b = rowBase >> 11;
    int t0 = rowBase & (Tt - 1);

#pragma unroll
    for (int p = 0; p < 2; p++) {
        if ((warp_n >> 1) == p) {
#pragma unroll
            for (int mi = 0; mi < 4; mi++) {
#pragma unroll
                for (int ni = 0; ni < 4; ni++) {
                    int rl = warp_m * 64 + mi * 16 + g;          // local t
                    int cl = warp_n * 32 + ni * 8 + 2 * tk;      // local d (0..127)
                    int cls = cl - p * 64;                       // 0..63
                    int t0g = (rowBase + rl) & (Tt - 1);
                    int t1g = (rowBase + rl + 8) & (Tt - 1);
                    int c0 = colBase + cl, c1 = c0 + 1;
                    SE[cls * 132 + rl]           = acc[mi][ni][0] + bias[c0] + freq[(size_t)t0g * Dd + c0];
                    SE[(cls + 1) * 132 + rl]     = acc[mi][ni][1] + bias[c1] + freq[(size_t)t0g * Dd + c1];
                    SE[cls * 132 + rl + 8]       = acc[mi][ni][2] + bias[c0] + freq[(size_t)t1g * Dd + c0];
                    SE[(cls + 1) * 132 + rl + 8] = acc[mi][ni][3] + bias[c1] + freq[(size_t)t1g * Dd + c1];
                }
            }
        }
        __syncthreads();
#pragma unroll
        for (int i = 0; i < 8; i++) {
            int idx = i * 256 + tid;     // 0..2047
            int dr = idx >> 5;           // 0..63
            int w  = idx & 31;
            float4 v = *(float4*)&SE[dr * 132 + w * 4];
            *(float4*)&g_ht[((size_t)(b * Dd) + colBase + p * 64 + dr) * Tt + t0 + w * 4] = v;
        }
        __syncthreads();
    }
}

// ---------------------------------------------------------------------------
// Fused 4-layer S4 stack (R8 state — best measured). Block = 128 thr.
// ---------------------------------------------------------------------------
__global__ __launch_bounds__(128, 7)
void s4_stack_kernel(const float* __restrict__ D_skip) {
    __shared__ float sx[NCH * SXS];     // 8.7 KB
    __shared__ float us[DBLK * Tt];     // 16 KB

    int tid  = threadIdx.x;
    int dl   = tid & 1;
    int c    = tid >> 1;
    int b    = blockIdx.x >> 8;
    int dblk = blockIdx.x & 255;
    int d    = dblk * DBLK + dl;
    int rot  = tid & 31;
    int chanbase = dl * Tt + c * TC;

    int seg = tid & 3;
    int dn  = tid >> 2;
    int dl2 = dn >> 4, n2 = dn & 15;

    const float4* gb4 = (const float4*)(g_ht + ((size_t)(b * Dd) + dblk * DBLK) * Tt);
#pragma unroll
    for (int j = 0; j < 8; j++) {
        int p = j * 128 + tid;
        float4 v = gb4[p];
        int ch = p >> 9;
        int t  = (p & 511) << 2;
        int base = ch * Tt + (t & ~31);
        int rr = (((t >> 5) << 1) + ch) & 31;
        int i0 = t & 31;
        us[base + ((i0 + 0) ^ rr)] = v.x;
        us[base + ((i0 + 1) ^ rr)] = v.y;
        us[base + ((i0 + 2) ^ rr)] = v.z;
        us[base + ((i0 + 3) ^ rr)] = v.w;
    }
    __syncthreads();

#pragma unroll 1
    for (int l = 0; l < Ll; l++) {
        ull a2[8];
        {
            const float4* ap4 = (const float4*)(g_Abar + (size_t)l * DN + d * Nn);
#pragma unroll
            for (int q = 0; q < 4; q++) {
                float4 v = ap4[q];
                a2[2*q]   = pack2(v.x, v.y);
                a2[2*q+1] = pack2(v.z, v.w);
            }
        }

        ull z2[8];
#pragma unroll
        for (int q = 0; q < 8; q++) z2[q] = 0ull;
#pragma unroll
        for (int i = 0; i < TC; i++) {
            float uu = us[chanbase + (i ^ rot)];
            ull u2 = pack2(uu, uu);
#pragma unroll
            for (int q = 0; q < 8; q++)
                z2[q] = fma2(a2[q], z2[q], u2);
        }
        {
            ull* so = (ull*)(sx + c * SXS + dl * Nn);
#pragma unroll
            for (int q = 0; q < 8; q++) so[q] = z2[q];
        }
        __syncthreads();

        {
            float ap = g_AbarP[(size_t)l * DN + (dblk * DBLK + dl2) * Nn + n2];

            float F = 0.0f;
#pragma unroll
            for (int j = 0; j < 16; j++)
                F = fmaf(ap, F, sx[(seg * 16 + j) * SXS + dn]);

            float p2 = ap * ap, p4 = p2 * p2, p8 = p4 * p4;
            float m  = p8 * p8;

            float Fp = __shfl_up_sync(0xffffffffu, F, 1, 4);
            float mp = __shfl_up_sync(0xffffffffu, m, 1, 4);
            if (seg >= 1) { F = fmaf(m, Fp, F); m *= mp; }
            Fp = __shfl_up_sync(0xffffffffu, F, 2, 4);
            mp = __shfl_up_sync(0xffffffffu, m, 2, 4);
            if (seg >= 2) { F = fmaf(m, Fp, F); m *= mp; }

            float carry = __shfl_up_sync(0xffffffffu, F, 1, 4);
            if (seg == 0) carry = 0.0f;

            float xs = carry;
            float fcur = sx[(seg * 16) * SXS + dn];
#pragma unroll
            for (int j = 0; j < 16; j++) {
                float fnext = (j < 15) ? sx[(seg * 16 + j + 1) * SXS + dn] : 0.0f;
                sx[(seg * 16 + j) * SXS + dn] = xs;
                xs = fmaf(ap, xs, fcur);
                fcur = fnext;
            }
        }
        __syncthreads();

        ull cb2[8];
        {
            const float4* cp4 = (const float4*)(g_CB + (size_t)l * DN + d * Nn);
#pragma unroll
            for (int q = 0; q < 4; q++) {
                float4 v = cp4[q];
                cb2[2*q]   = pack2(v.x, v.y);
                cb2[2*q+1] = pack2(v.z, v.w);
            }
        }
        float dsk = D_skip[l * Dd + d];

        {
            const ull* si = (const ull*)(sx + c * SXS + dl * Nn);
#pragma unroll
            for (int q = 0; q < 8; q++) z2[q] = si[q];
        }

#pragma unroll
        for (int i = 0; i < TC; i++) {
            float uu = us[chanbase + (i ^ rot)];
            ull u2 = pack2(uu, uu);
            ull y2 = 0ull;
#pragma unroll
            for (int q = 0; q < 8; q++) {
                z2[q] = fma2(a2[q], z2[q], u2);
                y2 = fma2(z2[q], cb2[q], y2);
            }
            float ylo, yhi; unpack2(y2, ylo, yhi);
            float y = ylo + yhi;
            y = fmaf(dsk, uu, y);
            float yy = y * y;
            float inner2 = 1.5957691216057308f * (y + 0.044715f * y * yy);
            float e = __expf(-inner2);
            float g = __fdividef(y, 1.0f + e);
            us[chanbase + (i ^ rot)] = uu + g;
        }
    }
    __syncthreads();

    float4* gb4o = (float4*)(g_ht + ((size_t)(b * Dd) + dblk * DBLK) * Tt);
#pragma unroll
    for (int j = 0; j < 8; j++) {
        int p = j * 128 + tid;
        int ch = p >> 9;
        int t  = (p & 511) << 2;
        int base = ch * Tt + (t & ~31);
        int rr = (((t >> 5) << 1) + ch) & 31;
        int i0 = t & 31;
        float4 v;
        v.x = us[base + ((i0 + 0) ^ rr)];
        v.y = us[base + ((i0 + 1) ^ rr)];
        v.z = us[base + ((i0 + 2) ^ rr)];
        v.w = us[base + ((i0 + 3) ^ rr)];
        gb4o[p] = v;
    }
}

// ---------------------------------------------------------------------------
// Head on transposed layout, single pass.
// ---------------------------------------------------------------------------
__global__ __launch_bounds__(256)
void head_kernel(const float* __restrict__ b_f0, const float* __restrict__ b_en,
                 float* __restrict__ out) {
    __shared__ float sh[8][4][32];
    int tid = threadIdx.x;
    int tt = tid & 31, oct = tid >> 5;
    int rowBase = blockIdx.x * 32;
    int b = rowBase >> 11, t0 = rowBase & (Tt - 1);

    const float* hp = g_ht + ((size_t)(b * Dd) + oct * 64) * Tt + t0 + tt;
    const float* swf = g_swf0 + oct * 64;
    const float* swe = g_swen + oct * 64;

    float s1 = 0.0f, s2 = 0.0f, sf = 0.0f, se = 0.0f;
#pragma unroll 8
    for (int dd = 0; dd < 64; dd++) {
        float v = hp[(size_t)dd * Tt];
        s1 += v;
        s2 = fmaf(v, v, s2);
        sf = fmaf(v, __ldg(swf + dd), sf);
        se = fmaf(v, __ldg(swe + dd), se);
    }
    sh[oct][0][tt] = s1; sh[oct][1][tt] = s2;
    sh[oct][2][tt] = sf; sh[oct][3][tt] = se;
    __syncthreads();

    if (tid < 32) {
        float a0 = 0.0f, a1 = 0.0f, a2 = 0.0f, a3 = 0.0f;
#pragma unroll
        for (int o = 0; o < 8; o++) {
            a0 += sh[o][0][tt]; a1 += sh[o][1][tt];
            a2 += sh[o][2][tt]; a3 += sh[o][3][tt];
        }
        float mu = a0 * (1.0f / Dd);
        float var = a1 * (1.0f / Dd) - mu * mu;
        float rstd = rsqrtf(var + 1e-5f);
        out[rowBase + tt]                   = rstd * (a2 - mu * g_hc[0]) + g_hc[1] + b_f0[0];
        out[(size_t)Bb * Tt + rowBase + tt] = rstd * (a3 - mu * g_hc[2]) + g_hc[3] + b_en[0];
    }
}

// ---------------------------------------------------------------------------
extern "C" void kernel_launch(void* const* d_in, const int* in_sizes, int n_in,
                              void* d_out, int out_size) {
    const float* text_emb = (const float*)d_in[0];
    const float* W_in     = (const float*)d_in[1];
    const float* b_in     = (const float*)d_in[2];
    const float* freq_pe  = (const float*)d_in[3];
    const float* A_log    = (const float*)d_in[4];
    const float* B_ssm    = (const float*)d_in[5];
    const float* C_ssm    = (const float*)d_in[6];
    const float* log_dt   = (const float*)d_in[7];
    const float* D_skip   = (const float*)d_in[8];
    const float* ln_f0_s  = (const float*)d_in[9];
    const float* ln_f0_b  = (const float*)d_in[10];
    const float* W_f0     = (const float*)d_in[11];
    const float* b_f0     = (const float*)d_in[12];
    const float* ln_en_s  = (const float*)d_in[13];
    const float* ln_en_b  = (const float*)d_in[14];
    const float* W_en     = (const float*)d_in[15];
    const float* b_en     = (const float*)d_in[16];
    float* out = (float*)d_out;

    precompute_kernel<<<(Ll * DN + 255) / 256, 256>>>(A_log, B_ssm, C_ssm, log_dt);
    head_prep_kernel<<<1, Dd>>>(ln_f0_s, ln_f0_b, W_f0, ln_en_s, ln_en_b, W_en);

    dim3 wtgrid(Dd / 32, Ee / 32);
    wt_prep_kernel<<<wtgrid, dim3(32, 8)>>>(W_in);

    dim3 ggrid(Dd / 128, (Bb * Tt) / 128);
    gemm_tf32_kernel<<<ggrid, 256>>>(text_emb, b_in, freq_pe);

    s4_stack_kernel<<<Bb * (Dd / DBLK), 128>>>(D_skip);

    head_kernel<<<(Bb * Tt) / 32, 256>>>(b_f0, b_en, out);
}

// round 10
// speedup vs baseline: 1.1685x; 1.0023x over previous
#include <cuda_runtime.h>
#include <math.h>
#include <stdint.h>

// Problem constants
#define Bb   4
#define Tt   2048
#define Ee   512
#define Dd   512
#define Nn   16
#define Ll   4
#define TC   32              // chunk length (time steps per thread)
#define NCH  (Tt / TC)       // 64 chunks
#define DN   (Dd * Nn)       // 8192
#define DBLK 2               // d-channels per block in fused scan
#define SXS  34              // padded smem row stride (floats, even for ull)

typedef unsigned long long ull;

__device__ __forceinline__ ull pack2(float lo, float hi) {
    ull r; asm("mov.b64 %0, {%1,%2};" : "=l"(r) : "f"(lo), "f"(hi)); return r;
}
__device__ __forceinline__ void unpack2(ull v, float& lo, float& hi) {
    asm("mov.b64 {%0,%1}, %2;" : "=f"(lo), "=f"(hi) : "l"(v));
}
__device__ __forceinline__ ull fma2(ull a, ull b, ull c) {
    ull d; asm("fma.rn.f32x2 %0, %1, %2, %3;" : "=l"(d) : "l"(a), "l"(b), "l"(c));
    return d;
}
__device__ __forceinline__ uint32_t f2tf(float f) {
    uint32_t u; asm("cvt.rna.tf32.f32 %0, %1;" : "=r"(u) : "f"(f)); return u;
}
__device__ __forceinline__ void ldsm4(uint32_t& r0, uint32_t& r1, uint32_t& r2,
                                      uint32_t& r3, const uint32_t* p) {
    uint32_t a = (uint32_t)__cvta_generic_to_shared(p);
    asm volatile("ldmatrix.sync.aligned.m8n8.x4.shared.b16 {%0,%1,%2,%3}, [%4];"
                 : "=r"(r0), "=r"(r1), "=r"(r2), "=r"(r3) : "r"(a));
}
__device__ __forceinline__ void mma_tf32(float* c, const uint32_t* a,
                                         uint32_t b0, uint32_t b1) {
    asm volatile("mma.sync.aligned.m16n8k8.row.col.f32.tf32.tf32.f32 "
                 "{%0,%1,%2,%3}, {%4,%5,%6,%7}, {%8,%9}, {%0,%1,%2,%3};"
                 : "+f"(c[0]), "+f"(c[1]), "+f"(c[2]), "+f"(c[3])
                 : "r"(a[0]), "r"(a[1]), "r"(a[2]), "r"(a[3]), "r"(b0), "r"(b1));
}
__device__ __forceinline__ void cp_async16(uint32_t dst_smem, const void* src) {
    asm volatile("cp.async.cg.shared.global [%0], [%1], 16;"
                 :: "r"(dst_smem), "l"(src));
}
__device__ __forceinline__ void cp_commit() {
    asm volatile("cp.async.commit_group;");
}
__device__ __forceinline__ void cp_wait0() {
    asm volatile("cp.async.wait_group 0;");
}

// Scratch (static device globals; no runtime allocation)
__device__ float g_ht[(size_t)Bb * Dd * Tt];       // residual stream, TRANSPOSED [b][d][t]
__device__ uint32_t g_Wt[(size_t)Dd * Ee];         // W transposed, tf32 [d][e]
__device__ float g_bf[(size_t)Dd * Tt];            // bias[d] + freq[t][d], [d][t]
__device__ float g_Abar [Ll * DN];
__device__ float g_CB   [Ll * DN];                 // C * Bbar
__device__ float g_AbarP[Ll * DN];                 // Abar^TC
__device__ float g_swf0[Dd], g_swen[Dd];           // scale*weight per head
__device__ float g_hc[4];                          // SWf0, BWf0, SWen, BWen

// ---------------------------------------------------------------------------
// Precompute per-layer SSM constants
// ---------------------------------------------------------------------------
__global__ void precompute_kernel(const float* __restrict__ A_log,
                                  const float* __restrict__ B_ssm,
                                  const float* __restrict__ C_ssm,
                                  const float* __restrict__ log_dt) {
    int idx = blockIdx.x * blockDim.x + threadIdx.x;
    if (idx >= Ll * DN) return;
    int l  = idx / DN;
    int dn = idx % DN;
    int d  = dn / Nn;
    float dt = expf(log_dt[l * Dd + d]);
    float A  = -expf(A_log[idx]);
    float dA = dt * A;
    float ab = expf(dA);
    g_Abar [idx] = ab;
    g_CB   [idx] = (ab - 1.0f) / A * B_ssm[idx] * C_ssm[idx];
    g_AbarP[idx] = expf(dA * (float)TC);
}

// ---------------------------------------------------------------------------
// W transpose + tf32 convert: g_Wt[d][e] = tf32(W[e][d])
// ---------------------------------------------------------------------------
__global__ void wt_prep_kernel(const float* __restrict__ W) {
    __shared__ float tile[32][33];
    int tx = threadIdx.x, ty = threadIdx.y;     // (32, 8)
    int d0 = blockIdx.x * 32, e0 = blockIdx.y * 32;
#pragma unroll
    for (int j = 0; j < 4; j++)
        tile[ty + j * 8][tx] = W[(size_t)(e0 + ty + j * 8) * Dd + d0 + tx];
    __syncthreads();
#pragma unroll
    for (int j = 0; j < 4; j++)
        g_Wt[(size_t)(d0 + ty + j * 8) * Ee + e0 + tx] = f2tf(tile[tx][ty + j * 8]);
}

// ---------------------------------------------------------------------------
// bias+freq transpose: g_bf[d][t] = bias[d] + freq[t][d]
// ---------------------------------------------------------------------------
__global__ void bf_prep_kernel(const float* __restrict__ bias,
                               const float* __restrict__ freq) {
    __shared__ float tile[32][33];
    int tx = threadIdx.x, ty = threadIdx.y;     // (32, 8)
    int d0 = blockIdx.x * 32, t0 = blockIdx.y * 32;
#pragma unroll
    for (int j = 0; j < 4; j++)
        tile[ty + j * 8][tx] = freq[(size_t)(t0 + ty + j * 8) * Dd + d0 + tx];
    __syncthreads();
#pragma unroll
    for (int j = 0; j < 4; j++)
        g_bf[(size_t)(d0 + ty + j * 8) * Tt + t0 + tx] =
            tile[tx][ty + j * 8] + bias[d0 + ty + j * 8];
}

// ---------------------------------------------------------------------------
// Head precompute
// ---------------------------------------------------------------------------
__global__ void head_prep_kernel(const float* __restrict__ s_f0, const float* __restrict__ bi_f0,
                                 const float* __restrict__ w_f0,
                                 const float* __restrict__ s_en, const float* __restrict__ bi_en,
                                 const float* __restrict__ w_en) {
    __shared__ float red[4][16];
    int d = threadIdx.x;                 // 512 threads
    float wf = w_f0[d], we = w_en[d];
    float v0 = s_f0[d] * wf;
    float v1 = bi_f0[d] * wf;
    float v2 = s_en[d] * we;
    float v3 = bi_en[d] * we;
    g_swf0[d] = v0; g_swen[d] = v2;

    float v[4] = {v0, v1, v2, v3};
    int lane = d & 31, w = d >> 5;
#pragma unroll
    for (int j = 0; j < 4; j++) {
        float x = v[j];
#pragma unroll
        for (int o = 16; o > 0; o >>= 1) x += __shfl_xor_sync(0xffffffffu, x, o);
        if (lane == 0) red[j][w] = x;
    }
    __syncthreads();
    if (d < 4) {
        float s = 0.0f;
#pragma unroll
        for (int k = 0; k < 16; k++) s += red[d][k];
        g_hc[d] = s;
    }
}

// ---------------------------------------------------------------------------
// TF32 GEMM, 128x128x16 tiles. 256 threads = 8 warps (2m x 4n), warp tile 64x32.
// B via cp.async from pre-converted g_Wt; A cvt in-flight via registers.
// Epilogue: raw acc -> smem transpose -> += g_bf (coalesced) -> g_ht.
// ---------------------------------------------------------------------------
#define AST 20     // smem row stride (words)
#define BUFW 2560  // words per buffer (128 rows * 20)

__global__ __launch_bounds__(256, 2)
void gemm_tf32_kernel(const float* __restrict__ X) {
    __shared__ __align__(16) uint32_t smem[4 * BUFW];   // As[2] then Bs[2] = 40960 B
    uint32_t* As = smem;
    uint32_t* Bs = smem + 2 * BUFW;

    int tid = threadIdx.x;
    int lane = tid & 31, wid = tid >> 5;
    int warp_m = wid >> 2, warp_n = wid & 3;
    int rowBase = blockIdx.y * 128;      // t rows
    int colBase = blockIdx.x * 128;      // d cols

    float acc[4][4][4];
#pragma unroll
    for (int i = 0; i < 4; i++)
#pragma unroll
        for (int j = 0; j < 4; j++)
#pragma unroll
            for (int k = 0; k < 4; k++) acc[i][j][k] = 0.0f;

    // ldmatrix per-lane addressing
    int a_row = (lane & 7) + ((lane >> 3) & 1) * 8;
    int a_colw = (lane >> 4) * 4;
    const uint32_t* aPtr = As + (warp_m * 64 + a_row) * AST + a_colw;
    int b_row = (lane & 7) + ((lane >> 4) << 3);
    int b_colw = ((lane >> 3) & 1) * 4;
    const uint32_t* bPtr = Bs + (warp_n * 32 + b_row) * AST + b_colw;

    // gmem->smem mapping (tiles are 128 rows x 16 words)
    int frow = tid >> 2;                 // 0..63 (and +64)
    int fcol = (tid & 3) << 2;           // word 0,4,8,12

    const float* Xp = X + (size_t)rowBase * Ee;
    const uint32_t* Wp = g_Wt + (size_t)colBase * Ee;

    uint32_t bs0 = (uint32_t)__cvta_generic_to_shared(&Bs[frow * AST + fcol]);
    uint32_t bs1 = (uint32_t)__cvta_generic_to_shared(&Bs[(frow + 64) * AST + fcol]);

    // prologue: ktile 0 -> buf 0
    {
        float4 va0 = *(const float4*)(Xp + (size_t)frow * Ee + fcol);
        float4 va1 = *(const float4*)(Xp + (size_t)(frow + 64) * Ee + fcol);
        *(uint4*)&As[frow * AST + fcol] =
            make_uint4(f2tf(va0.x), f2tf(va0.y), f2tf(va0.z), f2tf(va0.w));
        *(uint4*)&As[(frow + 64) * AST + fcol] =
            make_uint4(f2tf(va1.x), f2tf(va1.y), f2tf(va1.z), f2tf(va1.w));
        cp_async16(bs0, Wp + (size_t)frow * Ee + fcol);
        cp_async16(bs1, Wp + (size_t)(frow + 64) * Ee + fcol);
        cp_commit();
        cp_wait0();
    }
    __syncthreads();

    int buf = 0;
    for (int kt = 16; kt < Ee; kt += 16) {
        int nb = buf ^ 1;
        // prefetch next ktile: B via cp.async, A via registers
        cp_async16(bs0 + nb * (BUFW * 4), Wp + (size_t)frow * Ee + kt + fcol);
        cp_async16(bs1 + nb * (BUFW * 4), Wp + (size_t)(frow + 64) * Ee + kt + fcol);
        cp_commit();
        float4 va0 = *(const float4*)(Xp + (size_t)frow * Ee + kt + fcol);
        float4 va1 = *(const float4*)(Xp + (size_t)(frow + 64) * Ee + kt + fcol);

        // compute current buffer: batch all ldsm, then all mma
        const uint32_t* aB = aPtr + buf * BUFW;
        const uint32_t* bB = bPtr + buf * BUFW;
        uint32_t a[2][4][4], bb[2][2][4];
#pragma unroll
        for (int k8 = 0; k8 < 2; k8++) {
#pragma unroll
            for (int mi = 0; mi < 4; mi++)
                ldsm4(a[k8][mi][0], a[k8][mi][1], a[k8][mi][2], a[k8][mi][3],
                      aB + mi * (16 * AST) + k8 * 8);
#pragma unroll
            for (int nj = 0; nj < 2; nj++)
                ldsm4(bb[k8][nj][0], bb[k8][nj][1], bb[k8][nj][2], bb[k8][nj][3],
                      bB + nj * (16 * AST) + k8 * 8);
        }
#pragma unroll
        for (int k8 = 0; k8 < 2; k8++)
#pragma unroll
            for (int mi = 0; mi < 4; mi++)
#pragma unroll
                for (int nj = 0; nj < 2; nj++) {
                    mma_tf32(acc[mi][2 * nj + 0], a[k8][mi], bb[k8][nj][0], bb[k8][nj][1]);
                    mma_tf32(acc[mi][2 * nj + 1], a[k8][mi], bb[k8][nj][2], bb[k8][nj][3]);
                }

        // store prefetched A
        *(uint4*)&As[nb * BUFW + frow * AST + fcol] =
            make_uint4(f2tf(va0.x), f2tf(va0.y), f2tf(va0.z), f2tf(va0.w));
        *(uint4*)&As[nb * BUFW + (frow + 64) * AST + fcol] =
            make_uint4(f2tf(va1.x), f2tf(va1.y), f2tf(va1.z), f2tf(va1.w));
        cp_wait0();
        __syncthreads();
        buf = nb;
    }

    // last ktile
    {
        const uint32_t* aB = aPtr + buf * BUFW;
        const uint32_t* bB = bPtr + buf * BUFW;
        uint32_t a[2][4][4], bb[2][2][4];
#pragma unroll
        for (int k8 = 0; k8 < 2; k8++) {
#pragma unroll
            for (int mi = 0; mi < 4; mi++)
                ldsm4(a[k8][mi][0], a[k8][mi][1], a[k8][mi][2], a[k8][mi][3],
                      aB + mi * (16 * AST) + k8 * 8);
#pragma unroll
            for (int nj = 0; nj < 2; nj++)
                ldsm4(bb[k8][nj][0], bb[k8][nj][1], bb[k8][nj][2], bb[k8][nj][3],
                      bB + nj * (16 * AST) + k8 * 8);
        }
#pragma unroll
        for (int k8 = 0; k8 < 2; k8++)
#pragma unroll
            for (int mi = 0; mi < 4; mi++)
#pragma unroll
                for (int nj = 0; nj < 2; nj++) {
                    mma_tf32(acc[mi][2 * nj + 0], a[k8][mi], bb[k8][nj][0], bb[k8][nj][1]);
                    mma_tf32(acc[mi][2 * nj + 1], a[k8][mi], bb[k8][nj][2], bb[k8][nj][3]);
                }
    }
    __syncthreads();

    // Epilogue: two passes of 64 d-columns through smem transpose, then
    // coalesced add of g_bf[d][t] during the global store.
    float* SE = (float*)smem;            // [64][132] floats
    int g = lane >> 2, tk = lane & 3;
    int b = rowBase >> 11;
    int t0 = rowBase & (Tt - 1);

#pragma unroll
    for (int p = 0; p < 2; p++) {
        if ((warp_n >> 1) == p) {
#pragma unroll
            for (int mi = 0; mi < 4; mi++) {
#pragma unroll
                for (int ni = 0; ni < 4; ni++) {
                    int rl = warp_m * 64 + mi * 16 + g;          // local t
                    int cl = warp_n * 32 + ni * 8 + 2 * tk;      // local d (0..127)
                    int cls = cl - p * 64;                       // 0..63
                    SE[cls * 132 + rl]           = acc[mi][ni][0];
                    SE[(cls + 1) * 132 + rl]     = acc[mi][ni][1];
                    SE[cls * 132 + rl + 8]       = acc[mi][ni][2];
                    SE[(cls + 1) * 132 + rl + 8] = acc[mi][ni][3];
                }
            }
        }
        __syncthreads();
#pragma unroll
        for (int i = 0; i < 8; i++) {
            int idx = i * 256 + tid;     // 0..2047
            int dr = idx >> 5;           // 0..63
            int w  = idx & 31;
            int dg = colBase + p * 64 + dr;
            float4 v = *(float4*)&SE[dr * 132 + w * 4];
            float4 bf = *(const float4*)&g_bf[(size_t)dg * Tt + t0 + w * 4];
            v.x += bf.x; v.y += bf.y; v.z += bf.z; v.w += bf.w;
            *(float4*)&g_ht[((size_t)(b * Dd) + dg) * Tt + t0 + w * 4] = v;
        }
        __syncthreads();
    }
}

// ---------------------------------------------------------------------------
// Fused 4-layer S4 stack (R8 state — best measured). Block = 128 thr.
// ---------------------------------------------------------------------------
__global__ __launch_bounds__(128, 7)
void s4_stack_kernel(const float* __restrict__ D_skip) {
    __shared__ float sx[NCH * SXS];     // 8.7 KB
    __shared__ float us[DBLK * Tt];     // 16 KB

    int tid  = threadIdx.x;
    int dl   = tid & 1;
    int c    = tid >> 1;
    int b    = blockIdx.x >> 8;
    int dblk = blockIdx.x & 255;
    int d    = dblk * DBLK + dl;
    int rot  = tid & 31;
    int chanbase = dl * Tt + c * TC;

    int seg = tid & 3;
    int dn  = tid >> 2;
    int dl2 = dn >> 4, n2 = dn & 15;

    const float4* gb4 = (const float4*)(g_ht + ((size_t)(b * Dd) + dblk * DBLK) * Tt);
#pragma unroll
    for (int j = 0; j < 8; j++) {
        int p = j * 128 + tid;
        float4 v = gb4[p];
        int ch = p >> 9;
        int t  = (p & 511) << 2;
        int base = ch * Tt + (t & ~31);
        int rr = (((t >> 5) << 1) + ch) & 31;
        int i0 = t & 31;
        us[base + ((i0 + 0) ^ rr)] = v.x;
        us[base + ((i0 + 1) ^ rr)] = v.y;
        us[base + ((i0 + 2) ^ rr)] = v.z;
        us[base + ((i0 + 3) ^ rr)] = v.w;
    }
    __syncthreads();

#pragma unroll 1
    for (int l = 0; l < Ll; l++) {
        ull a2[8];
        {
            const float4* ap4 = (const float4*)(g_Abar + (size_t)l * DN + d * Nn);
#pragma unroll
            for (int q = 0; q < 4; q++) {
                float4 v = ap4[q];
                a2[2*q]   = pack2(v.x, v.y);
                a2[2*q+1] = pack2(v.z, v.w);
            }
        }

        ull z2[8];
#pragma unroll
        for (int q = 0; q < 8; q++) z2[q] = 0ull;
#pragma unroll
        for (int i = 0; i < TC; i++) {
            float uu = us[chanbase + (i ^ rot)];
            ull u2 = pack2(uu, uu);
#pragma unroll
            for (int q = 0; q < 8; q++)
                z2[q] = fma2(a2[q], z2[q], u2);
        }
        {
            ull* so = (ull*)(sx + c * SXS + dl * Nn);
#pragma unroll
            for (int q = 0; q < 8; q++) so[q] = z2[q];
        }
        __syncthreads();

        {
            float ap = g_AbarP[(size_t)l * DN + (dblk * DBLK + dl2) * Nn + n2];

            float F = 0.0f;
#pragma unroll
            for (int j = 0; j < 16; j++)
                F = fmaf(ap, F, sx[(seg * 16 + j) * SXS + dn]);

            float p2 = ap * ap, p4 = p2 * p2, p8 = p4 * p4;
            float m  = p8 * p8;

            float Fp = __shfl_up_sync(0xffffffffu, F, 1, 4);
            float mp = __shfl_up_sync(0xffffffffu, m, 1, 4);
            if (seg >= 1) { F = fmaf(m, Fp, F); m *= mp; }
            Fp = __shfl_up_sync(0xffffffffu, F, 2, 4);
            mp = __shfl_up_sync(0xffffffffu, m, 2, 4);
            if (seg >= 2) { F = fmaf(m, Fp, F); m *= mp; }

            float carry = __shfl_up_sync(0xffffffffu, F, 1, 4);
            if (seg == 0) carry = 0.0f;

            float xs = carry;
            float fcur = sx[(seg * 16) * SXS + dn];
#pragma unroll
            for (int j = 0; j < 16; j++) {
                float fnext = (j < 15) ? sx[(seg * 16 + j + 1) * SXS + dn] : 0.0f;
                sx[(seg * 16 + j) * SXS + dn] = xs;
                xs = fmaf(ap, xs, fcur);
                fcur = fnext;
            }
        }
        __syncthreads();

        ull cb2[8];
        {
            const float4* cp4 = (const float4*)(g_CB + (size_t)l * DN + d * Nn);
#pragma unroll
            for (int q = 0; q < 4; q++) {
                float4 v = cp4[q];
                cb2[2*q]   = pack2(v.x, v.y);
                cb2[2*q+1] = pack2(v.z, v.w);
            }
        }
        float dsk = D_skip[l * Dd + d];

        {
            const ull* si = (const ull*)(sx + c * SXS + dl * Nn);
#pragma unroll
            for (int q = 0; q < 8; q++) z2[q] = si[q];
        }

#pragma unroll
        for (int i = 0; i < TC; i++) {
            float uu = us[chanbase + (i ^ rot)];
            ull u2 = pack2(uu, uu);
            ull y2 = 0ull;
#pragma unroll
            for (int q = 0; q < 8; q++) {
                z2[q] = fma2(a2[q], z2[q], u2);
                y2 = fma2(z2[q], cb2[q], y2);
            }
            float ylo, yhi; unpack2(y2, ylo, yhi);
            float y = ylo + yhi;
            y = fmaf(dsk, uu, y);
            float yy = y * y;
            float inner2 = 1.5957691216057308f * (y + 0.044715f * y * yy);
            float e = __expf(-inner2);
            float g = __fdividef(y, 1.0f + e);
            us[chanbase + (i ^ rot)] = uu + g;
        }
    }
    __syncthreads();

    float4* gb4o = (float4*)(g_ht + ((size_t)(b * Dd) + dblk * DBLK) * Tt);
#pragma unroll
    for (int j = 0; j < 8; j++) {
        int p = j * 128 + tid;
        int ch = p >> 9;
        int t  = (p & 511) << 2;
        int base = ch * Tt + (t & ~31);
        int rr = (((t >> 5) << 1) + ch) & 31;
        int i0 = t & 31;
        float4 v;
        v.x = us[base + ((i0 + 0) ^ rr)];
        v.y = us[base + ((i0 + 1) ^ rr)];
        v.z = us[base + ((i0 + 2) ^ rr)];
        v.w = us[base + ((i0 + 3) ^ rr)];
        gb4o[p] = v;
    }
}

// ---------------------------------------------------------------------------
// Head on transposed layout, single pass.
// ---------------------------------------------------------------------------
__global__ __launch_bounds__(256)
void head_kernel(const float* __restrict__ b_f0, const float* __restrict__ b_en,
                 float* __restrict__ out) {
    __shared__ float sh[8][4][32];
    int tid = threadIdx.x;
    int tt = tid & 31, oct = tid >> 5;
    int rowBase = blockIdx.x * 32;
    int b = rowBase >> 11, t0 = rowBase & (Tt - 1);

    const float* hp = g_ht + ((size_t)(b * Dd) + oct * 64) * Tt + t0 + tt;
    const float* swf = g_swf0 + oct * 64;
    const float* swe = g_swen + oct * 64;

    float s1 = 0.0f, s2 = 0.0f, sf = 0.0f, se = 0.0f;
#pragma unroll 8
    for (int dd = 0; dd < 64; dd++) {
        float v = hp[(size_t)dd * Tt];
        s1 += v;
        s2 = fmaf(v, v, s2);
        sf = fmaf(v, __ldg(swf + dd), sf);
        se = fmaf(v, __ldg(swe + dd), se);
    }
    sh[oct][0][tt] = s1; sh[oct][1][tt] = s2;
    sh[oct][2][tt] = sf; sh[oct][3][tt] = se;
    __syncthreads();

    if (tid < 32) {
        float a0 = 0.0f, a1 = 0.0f, a2 = 0.0f, a3 = 0.0f;
#pragma unroll
        for (int o = 0; o < 8; o++) {
            a0 += sh[o][0][tt]; a1 += sh[o][1][tt];
            a2 += sh[o][2][tt]; a3 += sh[o][3][tt];
        }
        float mu = a0 * (1.0f / Dd);
        float var = a1 * (1.0f / Dd) - mu * mu;
        float rstd = rsqrtf(var + 1e-5f);
        out[rowBase + tt]                   = rstd * (a2 - mu * g_hc[0]) + g_hc[1] + b_f0[0];
        out[(size_t)Bb * Tt + rowBase + tt] = rstd * (a3 - mu * g_hc[2]) + g_hc[3] + b_en[0];
    }
}

// ---------------------------------------------------------------------------
extern "C" void kernel_launch(void* const* d_in, const int* in_sizes, int n_in,
                              void* d_out, int out_size) {
    const float* text_emb = (const float*)d_in[0];
    const float* W_in     = (const float*)d_in[1];
    const float* b_in     = (const float*)d_in[2];
    const float* freq_pe  = (const float*)d_in[3];
    const float* A_log    = (const float*)d_in[4];
    const float* B_ssm    = (const float*)d_in[5];
    const float* C_ssm    = (const float*)d_in[6];
    const float* log_dt   = (const float*)d_in[7];
    const float* D_skip   = (const float*)d_in[8];
    const float* ln_f0_s  = (const float*)d_in[9];
    const float* ln_f0_b  = (const float*)d_in[10];
    const float* W_f0     = (const float*)d_in[11];
    const float* b_f0     = (const float*)d_in[12];
    const float* ln_en_s  = (const float*)d_in[13];
    const float* ln_en_b  = (const float*)d_in[14];
    const float* W_en     = (const float*)d_in[15];
    const float* b_en     = (const float*)d_in[16];
    float* out = (float*)d_out;

    precompute_kernel<<<(Ll * DN + 255) / 256, 256>>>(A_log, B_ssm, C_ssm, log_dt);
    head_prep_kernel<<<1, Dd>>>(ln_f0_s, ln_f0_b, W_f0, ln_en_s, ln_en_b, W_en);

    dim3 wtgrid(Dd / 32, Ee / 32);
    wt_prep_kernel<<<wtgrid, dim3(32, 8)>>>(W_in);
    dim3 bfgrid(Dd / 32, Tt / 32);
    bf_prep_kernel<<<bfgrid, dim3(32, 8)>>>(b_in, freq_pe);

    dim3 ggrid(Dd / 128, (Bb * Tt) / 128);
    gemm_tf32_kernel<<<ggrid, 256>>>(text_emb);

    s4_stack_kernel<<<Bb * (Dd / DBLK), 128>>>(D_skip);

    head_kernel<<<(Bb * Tt) / 32, 256>>>(b_f0, b_en, out);
}